// round 6
// baseline (speedup 1.0000x reference)
#include <cuda_runtime.h>
#include <cuda_bf16.h>

#define N_NODES 100000
#define N_EDGES 1600000
#define COUT 64
#define CIN 128
#define NBLK_SCAN 391   // ceil(100000/256)

// ---------------- scratch (no allocations allowed) ----------------
// All of these are zero at module load; k_fold re-zeros what must be zero
// at the start of the NEXT replay, so every graph replay sees identical state.
__device__ int   g_degi[N_NODES];                // edge in-degree (no self loop)
__device__ float g_dinv[N_NODES];
__device__ float g_xs[(size_t)N_NODES * COUT];   // xw (unscaled), gather source
__device__ int   g_off[N_NODES];                 // CSR offsets (global, final)
__device__ int   g_cnt[N_NODES];                 // fill counters -> in-degree
__device__ int   g_srow[N_EDGES];                // CSR-sorted source row ids
__device__ int   g_bsum[512];
__device__ int   g_flag[512];
__device__ float g_sums[COUT];
__device__ float g_sumsq[COUT];
__device__ float g_A[COUT];
__device__ float g_B[COUT];

// packed f32x2 helpers
__device__ __forceinline__ unsigned long long pack_dup(float x) {
    unsigned long long p;
    unsigned u = __float_as_uint(x);
    asm("mov.b64 %0, {%1, %1};" : "=l"(p) : "r"(u));
    return p;
}
__device__ __forceinline__ void ffma2(unsigned long long& d,
                                      unsigned long long a,
                                      unsigned long long b) {
    asm("fma.rn.f32x2 %0, %1, %2, %3;" : "=l"(d) : "l"(a), "l"(b), "l"(d));
}
__device__ __forceinline__ void unpack2(unsigned long long p, float& lo, float& hi) {
    unsigned a, b2;
    asm("mov.b64 {%0, %1}, %2;" : "=r"(a), "=r"(b2) : "l"(p));
    lo = __uint_as_float(a);
    hi = __uint_as_float(b2);
}

// ---------------- 1. degree count over targets (int) ----------------
__global__ void k_deg(const int* __restrict__ col) {
    int e = blockIdx.x * blockDim.x + threadIdx.x;
    if (e < N_EDGES) atomicAdd(&g_degi[col[e]], 1);
}

// ---------------- 2. single-pass scan (dinv + global CSR offsets) ------------
// 391 blocks all fit in one wave (occupancy >> 391 CTAs), so the parallel
// lookback spin cannot deadlock.
__global__ void __launch_bounds__(256) k_scan1() {
    __shared__ int s[256];
    __shared__ int r2[256];
    const int tid = threadIdx.x;
    const int bid = blockIdx.x;
    const int i = bid * 256 + tid;
    int v = 0;
    if (i < N_NODES) {
        v = g_degi[i];
        g_dinv[i] = rsqrtf((float)v + 1.0f);   // deg incl self loop
    }
    s[tid] = v;
    __syncthreads();
    #pragma unroll
    for (int d = 1; d < 256; d <<= 1) {
        int t = (tid >= d) ? s[tid - d] : 0;
        __syncthreads();
        s[tid] += t;
        __syncthreads();
    }
    // publish block total
    if (tid == 255) {
        atomicExch(&g_bsum[bid], s[255]);
        __threadfence();
        atomicExch(&g_flag[bid], 1);
    }
    // parallel lookback: each thread polls predecessors tid, tid+256, ...
    int p = 0;
    for (int k = tid; k < bid; k += 256) {
        while (atomicAdd(&g_flag[k], 0) == 0) { }
        p += atomicAdd(&g_bsum[k], 0);
    }
    r2[tid] = p;
    __syncthreads();
    #pragma unroll
    for (int d = 128; d > 0; d >>= 1) {
        if (tid < d) r2[tid] += r2[tid + d];
        __syncthreads();
    }
    if (i < N_NODES) g_off[i] = r2[0] + s[tid] - v;   // exclusive global offset
}

// ---------------- 3. bin edges into CSR (by target) ----------------
__global__ void k_bin(const int* __restrict__ rowIdx, const int* __restrict__ colIdx) {
    int e = blockIdx.x * blockDim.x + threadIdx.x;
    if (e < N_EDGES) {
        int c = colIdx[e];
        int p = atomicAdd(&g_cnt[c], 1);
        g_srow[g_off[c] + p] = rowIdx[e];
    }
}

// ---------------- 4. GEMM: xs = x @ W (unscaled; fully independent) ----------
#define XPAD 260
__global__ void __launch_bounds__(256, 2) k_gemm(const float* __restrict__ x,
                                                 const float* __restrict__ W) {
    extern __shared__ float smem[];
    float* sW = smem;              // 8192 floats
    float* sX = smem + 8192;       // 32 * 260 floats
    const int tid = threadIdx.x;
    const int base = blockIdx.x * 256;

    {
        const float4* W4 = (const float4*)W;
        float4* sW4 = (float4*)sW;
        #pragma unroll
        for (int i = tid; i < 2048; i += 256) sW4[i] = W4[i];
    }

    const int c0 = (tid & 7) * 8;
    const int r0 = (tid >> 3) * 8;

    unsigned long long acc[8][4];
    #pragma unroll
    for (int j = 0; j < 8; j++)
        #pragma unroll
        for (int p = 0; p < 4; p++) acc[j][p] = 0ULL;

    const float4* x4 = (const float4*)x;

    for (int cc = 0; cc < 4; cc++) {
        const int k0 = cc * 32;
        __syncthreads();
        #pragma unroll
        for (int t = 0; t < 8; t++) {
            int idx = tid + t * 256;
            int r = idx >> 3;
            int kq = idx & 7;
            int row = base + r;
            float4 v = make_float4(0.f, 0.f, 0.f, 0.f);
            if (row < N_NODES) v = x4[row * 32 + (k0 >> 2) + kq];
            int kl = kq << 2;
            sX[(kl + 0) * XPAD + r] = v.x;
            sX[(kl + 1) * XPAD + r] = v.y;
            sX[(kl + 2) * XPAD + r] = v.z;
            sX[(kl + 3) * XPAD + r] = v.w;
        }
        __syncthreads();

        #pragma unroll 4
        for (int kk = 0; kk < 32; kk++) {
            const int k = k0 + kk;
            ulonglong2 wp0 = *(const ulonglong2*)&sW[k * 64 + c0];
            ulonglong2 wp1 = *(const ulonglong2*)&sW[k * 64 + c0 + 4];
            unsigned long long wv[4] = {wp0.x, wp0.y, wp1.x, wp1.y};
            float4 xv0 = *(const float4*)&sX[kk * XPAD + r0];
            float4 xv1 = *(const float4*)&sX[kk * XPAD + r0 + 4];
            float xr[8] = {xv0.x, xv0.y, xv0.z, xv0.w, xv1.x, xv1.y, xv1.z, xv1.w};
            #pragma unroll
            for (int j = 0; j < 8; j++) {
                unsigned long long xd = pack_dup(xr[j]);
                #pragma unroll
                for (int p = 0; p < 4; p++) ffma2(acc[j][p], xd, wv[p]);
            }
        }
    }

    #pragma unroll
    for (int j = 0; j < 8; j++) {
        int row = base + r0 + j;
        if (row < N_NODES) {
            float o[8];
            #pragma unroll
            for (int p = 0; p < 4; p++) unpack2(acc[j][p], o[2 * p], o[2 * p + 1]);
            ((float4*)g_xs)[row * 16 + (c0 >> 2)] =
                make_float4(o[0], o[1], o[2], o[3]);
            ((float4*)g_xs)[row * 16 + (c0 >> 2) + 1] =
                make_float4(o[4], o[5], o[6], o[7]);
        }
    }
}

// ---------------- 5. CSR gather-aggregate + fused BN stats -------------------
// R3-style: 16 lanes per node, each lane loads the (broadcast) edge index and
// dinv[src] directly — HW coalesces identical addresses, no shfl needed.
__global__ void __launch_bounds__(256) k_agg(float* __restrict__ out,
                                             const float* __restrict__ b) {
    __shared__ float s1[COUT], s2m[COUT];
    const int tid = threadIdx.x;
    if (tid < COUT) { s1[tid] = 0.f; s2m[tid] = 0.f; }
    __syncthreads();

    const int gid = blockIdx.x * 256 + tid;
    float sum0 = 0.f, sum1 = 0.f, sum2 = 0.f, sum3 = 0.f;
    float sq0 = 0.f, sq1 = 0.f, sq2 = 0.f, sq3 = 0.f;
    const int comp = tid & 15;

    if (gid < N_NODES * 16) {
        const int node = gid >> 4;
        const float4* xs4 = (const float4*)g_xs;
        const float dn = g_dinv[node];

        float4 sv = xs4[node * 16 + comp];
        float4 acc = make_float4(sv.x * dn, sv.y * dn, sv.z * dn, sv.w * dn);

        const int beg = g_off[node];
        const int end = beg + g_cnt[node];
        int j = beg;
        for (; j + 4 <= end; j += 4) {
            int r0 = g_srow[j], r1 = g_srow[j + 1];
            int r2 = g_srow[j + 2], r3 = g_srow[j + 3];
            float d0 = g_dinv[r0], d1 = g_dinv[r1];
            float d2 = g_dinv[r2], d3 = g_dinv[r3];
            float4 a = xs4[r0 * 16 + comp];
            float4 bb4 = xs4[r1 * 16 + comp];
            float4 c = xs4[r2 * 16 + comp];
            float4 d = xs4[r3 * 16 + comp];
            acc.x += a.x * d0 + bb4.x * d1 + c.x * d2 + d.x * d3;
            acc.y += a.y * d0 + bb4.y * d1 + c.y * d2 + d.y * d3;
            acc.z += a.z * d0 + bb4.z * d1 + c.z * d2 + d.z * d3;
            acc.w += a.w * d0 + bb4.w * d1 + c.w * d2 + d.w * d3;
        }
        for (; j < end; j++) {
            int r = g_srow[j];
            float dr = g_dinv[r];
            float4 a = xs4[r * 16 + comp];
            acc.x += a.x * dr; acc.y += a.y * dr;
            acc.z += a.z * dr; acc.w += a.w * dr;
        }
        acc.x *= dn; acc.y *= dn; acc.z *= dn; acc.w *= dn;
        ((float4*)out)[gid] = acc;

        const float4 bv = ((const float4*)b)[comp];
        float o0 = acc.x + bv.x, o1 = acc.y + bv.y;
        float o2 = acc.z + bv.z, o3 = acc.w + bv.w;
        sum0 = o0; sq0 = o0 * o0;
        sum1 = o1; sq1 = o1 * o1;
        sum2 = o2; sq2 = o2 * o2;
        sum3 = o3; sq3 = o3 * o3;
    }

    const int cb = comp * 4;
    atomicAdd(&s1[cb + 0], sum0); atomicAdd(&s2m[cb + 0], sq0);
    atomicAdd(&s1[cb + 1], sum1); atomicAdd(&s2m[cb + 1], sq1);
    atomicAdd(&s1[cb + 2], sum2); atomicAdd(&s2m[cb + 2], sq2);
    atomicAdd(&s1[cb + 3], sum3); atomicAdd(&s2m[cb + 3], sq3);
    __syncthreads();
    if (tid < COUT) {
        atomicAdd(&g_sums[tid], s1[tid]);
        atomicAdd(&g_sumsq[tid], s2m[tid]);
    }
}

// ---------------- 6. fold BN into affine + re-zero scratch for next replay ---
__global__ void __launch_bounds__(256) k_fold(const float* __restrict__ b,
                                              const float* __restrict__ gamma,
                                              const float* __restrict__ beta) {
    const int bid = blockIdx.x;
    const int tid = threadIdx.x;
    if (bid == 0) {
        if (tid < COUT) {
            float inv_n = 1.0f / (float)N_NODES;
            float mean = g_sums[tid] * inv_n;
            float var = g_sumsq[tid] * inv_n - mean * mean;
            float scale = gamma[tid] * rsqrtf(var + 1e-5f);
            g_A[tid] = scale;
            g_B[tid] = scale * (b[tid] - mean) + beta[tid];
        }
        __syncthreads();
        if (tid < COUT) { g_sums[tid] = 0.f; g_sumsq[tid] = 0.f; }
        if (tid < 256) { /* fallthrough to shared zeroing below */ }
    }
    const int i = bid * 256 + tid;
    if (i < N_NODES) { g_degi[i] = 0; g_cnt[i] = 0; }
    if (i < 512) { g_flag[i] = 0; g_bsum[i] = 0; }
}

// ---------------- 7. final: y = leaky(A*v + B), in place ----------------
__global__ void __launch_bounds__(256) k_final(float* __restrict__ out) {
    int q = blockIdx.x * 256 + threadIdx.x;
    if (q >= N_NODES * 16) return;
    int cq = q & 15;
    float4 a = ((const float4*)g_A)[cq];
    float4 bb = ((const float4*)g_B)[cq];
    float4 v = ((float4*)out)[q];
    float4 y;
    y.x = a.x * v.x + bb.x;
    y.y = a.y * v.y + bb.y;
    y.z = a.z * v.z + bb.z;
    y.w = a.w * v.w + bb.w;
    y.x = (y.x >= 0.f) ? y.x : 0.01f * y.x;
    y.y = (y.y >= 0.f) ? y.y : 0.01f * y.y;
    y.z = (y.z >= 0.f) ? y.z : 0.01f * y.z;
    y.w = (y.w >= 0.f) ? y.w : 0.01f * y.w;
    ((float4*)out)[q] = y;
}

extern "C" void kernel_launch(void* const* d_in, const int* in_sizes, int n_in,
                              void* d_out, int out_size) {
    const float* x      = (const float*)d_in[0];
    const int*   eidx   = (const int*)d_in[1];     // [2, E]: row then col
    const float* W      = (const float*)d_in[2];
    const float* b      = (const float*)d_in[3];
    const float* gamma  = (const float*)d_in[4];
    const float* beta   = (const float*)d_in[5];
    float* out = (float*)d_out;

    const int* rowIdx = eidx;
    const int* colIdx = eidx + N_EDGES;

    static cudaStream_t s2 = 0;
    static cudaEvent_t evF = 0, evJ = 0;
    static bool init_done = false;
    const int gemm_smem = (8192 + 32 * XPAD) * sizeof(float);   // 66048 B
    if (!init_done) {
        cudaFuncSetAttribute(k_gemm, cudaFuncAttributeMaxDynamicSharedMemorySize, gemm_smem);
        if (cudaStreamCreateWithFlags(&s2, cudaStreamNonBlocking) != cudaSuccess) s2 = 0;
        if (cudaEventCreateWithFlags(&evF, cudaEventDisableTiming) != cudaSuccess) evF = 0;
        if (cudaEventCreateWithFlags(&evJ, cudaEventDisableTiming) != cudaSuccess) evJ = 0;
        init_done = true;
    }
    const bool fork = (s2 != 0) && (evF != 0) && (evJ != 0);

    // Fork: GEMM (independent of edges) runs on s2, overlapping the CSR build.
    if (fork) {
        cudaEventRecord(evF, 0);
        cudaStreamWaitEvent(s2, evF, 0);
        k_gemm<<<(N_NODES + 255) / 256, 256, gemm_smem, s2>>>(x, W);
    } else {
        k_gemm<<<(N_NODES + 255) / 256, 256, gemm_smem>>>(x, W);
    }

    // Main chain: degree -> scan (dinv + offsets) -> bin
    k_deg<<<(N_EDGES + 255) / 256, 256>>>(colIdx);
    k_scan1<<<NBLK_SCAN, 256>>>();
    k_bin<<<(N_EDGES + 255) / 256, 256>>>(rowIdx, colIdx);

    // Join
    if (fork) {
        cudaEventRecord(evJ, s2);
        cudaStreamWaitEvent(0, evJ, 0);
    }

    k_agg<<<(N_NODES * 16 + 255) / 256, 256>>>(out, b);
    k_fold<<<NBLK_SCAN + 1, 256>>>(b, gamma, beta);
    k_final<<<(N_NODES * 16 + 255) / 256, 256>>>(out);
}

// round 7
// speedup vs baseline: 1.0482x; 1.0482x over previous
#include <cuda_runtime.h>
#include <cuda_bf16.h>

#define N_NODES 100000
#define N_EDGES 1600000
#define COUT 64
#define CIN 128
#define NBLK_SCAN 391   // ceil(100000/256)

// ---------------- scratch (no allocations allowed) ----------------
// Zero at module load; k_fold re-zeros everything that must be zero before
// the next replay, so every graph replay sees identical initial state.
__device__ int   g_degi[N_NODES];                // edge in-degree (no self loop)
__device__ float g_dinv[N_NODES];
__device__ float g_xs[(size_t)N_NODES * COUT];   // (x@W) * dinv[row]
__device__ int   g_off[N_NODES];                 // CSR offsets (global)
__device__ int   g_cnt[N_NODES];                 // fill counters -> in-degree
__device__ int   g_srow[N_EDGES];                // CSR-sorted source row ids
__device__ int   g_bsum[512];
__device__ int   g_flag[512];
__device__ float g_sums[COUT];
__device__ float g_sumsq[COUT];
__device__ float g_A[COUT];
__device__ float g_B[COUT];

// packed f32x2 helpers
__device__ __forceinline__ unsigned long long pack_dup(float x) {
    unsigned long long p;
    unsigned u = __float_as_uint(x);
    asm("mov.b64 %0, {%1, %1};" : "=l"(p) : "r"(u));
    return p;
}
__device__ __forceinline__ void ffma2(unsigned long long& d,
                                      unsigned long long a,
                                      unsigned long long b) {
    asm("fma.rn.f32x2 %0, %1, %2, %3;" : "=l"(d) : "l"(a), "l"(b), "l"(d));
}
__device__ __forceinline__ void unpack2(unsigned long long p, float& lo, float& hi) {
    unsigned a, b2;
    asm("mov.b64 {%0, %1}, %2;" : "=r"(a), "=r"(b2) : "l"(p));
    lo = __uint_as_float(a);
    hi = __uint_as_float(b2);
}

// ---------------- 1. degree count: 4 edges/thread via int4 ----------------
__global__ void k_deg(const int* __restrict__ col) {
    int t = blockIdx.x * blockDim.x + threadIdx.x;
    if (t < N_EDGES / 4) {
        int4 c = ((const int4*)col)[t];
        atomicAdd(&g_degi[c.x], 1);
        atomicAdd(&g_degi[c.y], 1);
        atomicAdd(&g_degi[c.z], 1);
        atomicAdd(&g_degi[c.w], 1);
    }
}

// ---------------- 2. single-pass scan (dinv + global CSR offsets) ------------
// 391 blocks co-resident in one wave; nothing else runs concurrently, so the
// lookback spin cannot deadlock.
__global__ void __launch_bounds__(256) k_scan1() {
    __shared__ int s[256];
    __shared__ int r2[256];
    const int tid = threadIdx.x;
    const int bid = blockIdx.x;
    const int i = bid * 256 + tid;
    int v = 0;
    if (i < N_NODES) {
        v = g_degi[i];
        g_dinv[i] = rsqrtf((float)v + 1.0f);   // deg incl self loop
    }
    s[tid] = v;
    __syncthreads();
    #pragma unroll
    for (int d = 1; d < 256; d <<= 1) {
        int t = (tid >= d) ? s[tid - d] : 0;
        __syncthreads();
        s[tid] += t;
        __syncthreads();
    }
    if (tid == 255) {
        atomicExch(&g_bsum[bid], s[255]);
        __threadfence();
        atomicExch(&g_flag[bid], 1);
    }
    int p = 0;
    for (int k = tid; k < bid; k += 256) {
        while (atomicAdd(&g_flag[k], 0) == 0) { }
        p += atomicAdd(&g_bsum[k], 0);
    }
    r2[tid] = p;
    __syncthreads();
    #pragma unroll
    for (int d = 128; d > 0; d >>= 1) {
        if (tid < d) r2[tid] += r2[tid + d];
        __syncthreads();
    }
    if (i < N_NODES) g_off[i] = r2[0] + s[tid] - v;
}

// ---------------- 3. bin edges into CSR: 4 edges/thread via int4 -------------
__global__ void k_bin(const int* __restrict__ rowIdx, const int* __restrict__ colIdx) {
    int t = blockIdx.x * blockDim.x + threadIdx.x;
    if (t < N_EDGES / 4) {
        int4 r = ((const int4*)rowIdx)[t];
        int4 c = ((const int4*)colIdx)[t];
        int p0 = atomicAdd(&g_cnt[c.x], 1);
        int p1 = atomicAdd(&g_cnt[c.y], 1);
        int p2 = atomicAdd(&g_cnt[c.z], 1);
        int p3 = atomicAdd(&g_cnt[c.w], 1);
        g_srow[g_off[c.x] + p0] = r.x;
        g_srow[g_off[c.y] + p1] = r.y;
        g_srow[g_off[c.z] + p2] = r.z;
        g_srow[g_off[c.w] + p3] = r.w;
    }
}

// ---------------- 4. GEMM: xs = (x @ W) * dinv[row]  (runs after scan) -------
#define XPAD 260
__global__ void __launch_bounds__(256, 2) k_gemm(const float* __restrict__ x,
                                                 const float* __restrict__ W) {
    extern __shared__ float smem[];
    float* sW = smem;              // 8192 floats
    float* sX = smem + 8192;       // 32 * 260 floats
    const int tid = threadIdx.x;
    const int base = blockIdx.x * 256;

    {
        const float4* W4 = (const float4*)W;
        float4* sW4 = (float4*)sW;
        #pragma unroll
        for (int i = tid; i < 2048; i += 256) sW4[i] = W4[i];
    }

    const int c0 = (tid & 7) * 8;
    const int r0 = (tid >> 3) * 8;

    unsigned long long acc[8][4];
    #pragma unroll
    for (int j = 0; j < 8; j++)
        #pragma unroll
        for (int p = 0; p < 4; p++) acc[j][p] = 0ULL;

    const float4* x4 = (const float4*)x;

    for (int cc = 0; cc < 4; cc++) {
        const int k0 = cc * 32;
        __syncthreads();
        #pragma unroll
        for (int t = 0; t < 8; t++) {
            int idx = tid + t * 256;
            int r = idx >> 3;
            int kq = idx & 7;
            int row = base + r;
            float4 v = make_float4(0.f, 0.f, 0.f, 0.f);
            if (row < N_NODES) v = x4[row * 32 + (k0 >> 2) + kq];
            int kl = kq << 2;
            sX[(kl + 0) * XPAD + r] = v.x;
            sX[(kl + 1) * XPAD + r] = v.y;
            sX[(kl + 2) * XPAD + r] = v.z;
            sX[(kl + 3) * XPAD + r] = v.w;
        }
        __syncthreads();

        #pragma unroll 4
        for (int kk = 0; kk < 32; kk++) {
            const int k = k0 + kk;
            ulonglong2 wp0 = *(const ulonglong2*)&sW[k * 64 + c0];
            ulonglong2 wp1 = *(const ulonglong2*)&sW[k * 64 + c0 + 4];
            unsigned long long wv[4] = {wp0.x, wp0.y, wp1.x, wp1.y};
            float4 xv0 = *(const float4*)&sX[kk * XPAD + r0];
            float4 xv1 = *(const float4*)&sX[kk * XPAD + r0 + 4];
            float xr[8] = {xv0.x, xv0.y, xv0.z, xv0.w, xv1.x, xv1.y, xv1.z, xv1.w};
            #pragma unroll
            for (int j = 0; j < 8; j++) {
                unsigned long long xd = pack_dup(xr[j]);
                #pragma unroll
                for (int p = 0; p < 4; p++) ffma2(acc[j][p], xd, wv[p]);
            }
        }
    }

    #pragma unroll
    for (int j = 0; j < 8; j++) {
        int row = base + r0 + j;
        if (row < N_NODES) {
            float di = g_dinv[row];
            float o[8];
            #pragma unroll
            for (int p = 0; p < 4; p++) unpack2(acc[j][p], o[2 * p], o[2 * p + 1]);
            ((float4*)g_xs)[row * 16 + (c0 >> 2)] =
                make_float4(o[0] * di, o[1] * di, o[2] * di, o[3] * di);
            ((float4*)g_xs)[row * 16 + (c0 >> 2) + 1] =
                make_float4(o[4] * di, o[5] * di, o[6] * di, o[7] * di);
        }
    }
}

// ---------------- 5. CSR gather-aggregate (R3 loop) + fused BN stats ---------
__global__ void __launch_bounds__(256) k_agg(float* __restrict__ out,
                                             const float* __restrict__ b) {
    __shared__ float s1[COUT], s2m[COUT];
    const int tid = threadIdx.x;
    if (tid < COUT) { s1[tid] = 0.f; s2m[tid] = 0.f; }
    __syncthreads();

    const int gid = blockIdx.x * 256 + tid;
    const int comp = tid & 15;
    float sum0 = 0.f, sum1 = 0.f, sum2 = 0.f, sum3 = 0.f;
    float sq0 = 0.f, sq1 = 0.f, sq2 = 0.f, sq3 = 0.f;

    if (gid < N_NODES * 16) {
        const int node = gid >> 4;
        const float4* xs4 = (const float4*)g_xs;

        float4 acc = xs4[node * 16 + comp];   // self loop (already *dinv)
        const int beg = g_off[node];
        const int end = beg + g_cnt[node];
        int j = beg;
        for (; j + 4 <= end; j += 4) {
            int r0 = g_srow[j], r1 = g_srow[j + 1];
            int r2 = g_srow[j + 2], r3 = g_srow[j + 3];
            float4 a = xs4[r0 * 16 + comp];
            float4 bb = xs4[r1 * 16 + comp];
            float4 c = xs4[r2 * 16 + comp];
            float4 d = xs4[r3 * 16 + comp];
            acc.x += (a.x + bb.x) + (c.x + d.x);
            acc.y += (a.y + bb.y) + (c.y + d.y);
            acc.z += (a.z + bb.z) + (c.z + d.z);
            acc.w += (a.w + bb.w) + (c.w + d.w);
        }
        for (; j < end; j++) {
            float4 a = xs4[g_srow[j] * 16 + comp];
            acc.x += a.x; acc.y += a.y; acc.z += a.z; acc.w += a.w;
        }
        const float di = g_dinv[node];
        acc.x *= di; acc.y *= di; acc.z *= di; acc.w *= di;
        ((float4*)out)[gid] = acc;

        const float4 bv = ((const float4*)b)[comp];
        float o0 = acc.x + bv.x, o1 = acc.y + bv.y;
        float o2 = acc.z + bv.z, o3 = acc.w + bv.w;
        sum0 = o0; sq0 = o0 * o0;
        sum1 = o1; sq1 = o1 * o1;
        sum2 = o2; sq2 = o2 * o2;
        sum3 = o3; sq3 = o3 * o3;
    }

    const int cb = comp * 4;
    atomicAdd(&s1[cb + 0], sum0); atomicAdd(&s2m[cb + 0], sq0);
    atomicAdd(&s1[cb + 1], sum1); atomicAdd(&s2m[cb + 1], sq1);
    atomicAdd(&s1[cb + 2], sum2); atomicAdd(&s2m[cb + 2], sq2);
    atomicAdd(&s1[cb + 3], sum3); atomicAdd(&s2m[cb + 3], sq3);
    __syncthreads();
    if (tid < COUT) {
        atomicAdd(&g_sums[tid], s1[tid]);
        atomicAdd(&g_sumsq[tid], s2m[tid]);
    }
}

// ---------------- 6. fold BN + re-zero scratch for next replay ---------------
__global__ void __launch_bounds__(256) k_fold(const float* __restrict__ b,
                                              const float* __restrict__ gamma,
                                              const float* __restrict__ beta) {
    const int bid = blockIdx.x;
    const int tid = threadIdx.x;
    if (bid == 0 && tid < COUT) {
        float inv_n = 1.0f / (float)N_NODES;
        float mean = g_sums[tid] * inv_n;
        float var = g_sumsq[tid] * inv_n - mean * mean;
        float scale = gamma[tid] * rsqrtf(var + 1e-5f);
        g_A[tid] = scale;
        g_B[tid] = scale * (b[tid] - mean) + beta[tid];
        g_sums[tid] = 0.f;
        g_sumsq[tid] = 0.f;
    }
    const int i = bid * 256 + tid;
    if (i < N_NODES) { g_degi[i] = 0; g_cnt[i] = 0; }
    if (i < 512) { g_flag[i] = 0; g_bsum[i] = 0; }
}

// ---------------- 7. final: y = leaky(A*v + B), in place ----------------
__global__ void __launch_bounds__(256) k_final(float* __restrict__ out) {
    int q = blockIdx.x * 256 + threadIdx.x;
    if (q >= N_NODES * 16) return;
    int cq = q & 15;
    float4 a = ((const float4*)g_A)[cq];
    float4 bb = ((const float4*)g_B)[cq];
    float4 v = ((float4*)out)[q];
    float4 y;
    y.x = a.x * v.x + bb.x;
    y.y = a.y * v.y + bb.y;
    y.z = a.z * v.z + bb.z;
    y.w = a.w * v.w + bb.w;
    y.x = (y.x >= 0.f) ? y.x : 0.01f * y.x;
    y.y = (y.y >= 0.f) ? y.y : 0.01f * y.y;
    y.z = (y.z >= 0.f) ? y.z : 0.01f * y.z;
    y.w = (y.w >= 0.f) ? y.w : 0.01f * y.w;
    ((float4*)out)[q] = y;
}

extern "C" void kernel_launch(void* const* d_in, const int* in_sizes, int n_in,
                              void* d_out, int out_size) {
    const float* x      = (const float*)d_in[0];
    const int*   eidx   = (const int*)d_in[1];     // [2, E]: row then col
    const float* W      = (const float*)d_in[2];
    const float* b      = (const float*)d_in[3];
    const float* gamma  = (const float*)d_in[4];
    const float* beta   = (const float*)d_in[5];
    float* out = (float*)d_out;

    const int* rowIdx = eidx;
    const int* colIdx = eidx + N_EDGES;

    static cudaStream_t s2 = 0;
    static cudaEvent_t evF = 0, evJ = 0;
    static bool init_done = false;
    const int gemm_smem = (8192 + 32 * XPAD) * sizeof(float);   // 66048 B
    if (!init_done) {
        cudaFuncSetAttribute(k_gemm, cudaFuncAttributeMaxDynamicSharedMemorySize, gemm_smem);
        if (cudaStreamCreateWithFlags(&s2, cudaStreamNonBlocking) != cudaSuccess) s2 = 0;
        if (cudaEventCreateWithFlags(&evF, cudaEventDisableTiming) != cudaSuccess) evF = 0;
        if (cudaEventCreateWithFlags(&evJ, cudaEventDisableTiming) != cudaSuccess) evJ = 0;
        init_done = true;
    }
    const bool fork = (s2 != 0) && (evF != 0) && (evJ != 0);

    // chain: deg -> scan (dinv + offsets)
    k_deg<<<(N_EDGES / 4 + 255) / 256, 256>>>(colIdx);
    k_scan1<<<NBLK_SCAN, 256>>>();

    // fork: GEMM (needs dinv) overlaps bin
    if (fork) {
        cudaEventRecord(evF, 0);
        cudaStreamWaitEvent(s2, evF, 0);
        k_gemm<<<(N_NODES + 255) / 256, 256, gemm_smem, s2>>>(x, W);
    } else {
        k_gemm<<<(N_NODES + 255) / 256, 256, gemm_smem>>>(x, W);
    }

    k_bin<<<(N_EDGES / 4 + 255) / 256, 256>>>(rowIdx, colIdx);

    if (fork) {
        cudaEventRecord(evJ, s2);
        cudaStreamWaitEvent(0, evJ, 0);
    }

    k_agg<<<(N_NODES * 16 + 255) / 256, 256>>>(out, b);
    k_fold<<<NBLK_SCAN, 256>>>(b, gamma, beta);
    k_final<<<(N_NODES * 16 + 255) / 256, 256>>>(out);
}